// round 13
// baseline (speedup 1.0000x reference)
#include <cuda_runtime.h>
#include <cuda_bf16.h>
#include <cstdint>

// ============================================================
// BitFeedForward (Hadamard BitLinear x2) for sm_103
// R13: revert GEMM to R8 topology (BM=BN=128, 64x32 warp tile, 3 stages,
//      2 CTAs/SM) + software-pipeline B fragments across k16 steps.
//      R9's 64x64/1-CTA variant regressed (crossbar theory falsified).
// ============================================================

#define MDIM 8192          // B*S tokens
#define HK1  2048          // hidden (layer1 K)
#define HK2  4096          // intermediate (layer2 K)
#define WN   8388608       // elements per weight (4096*2048)

// -------------------- scratch (device globals; no allocs allowed) ---------
__device__ __align__(256) __nv_bfloat16 g_wq_up[WN];
__device__ __align__(256) __nv_bfloat16 g_wq_dn[WN];
__device__ __align__(256) __nv_bfloat16 g_xq[(size_t)MDIM * HK1];
__device__ __align__(256) float         g_h [(size_t)MDIM * HK2];
__device__ __align__(256) __nv_bfloat16 g_hq[(size_t)MDIM * HK2];
__device__ float g_m1[MDIM];
__device__ float g_m2[MDIM];
__device__ float g_ws[2];
__device__ float g_part[512];

// -------------------- PTX helpers ----------------------------------------
#define SWZ(o) ((o) ^ (((o) >> 3) & 0x70))

__device__ __forceinline__ uint32_t smem_u32(const void* p) {
    uint32_t a;
    asm("{ .reg .u64 t; cvta.to.shared.u64 t, %1; cvt.u32.u64 %0, t; }"
        : "=r"(a) : "l"(p));
    return a;
}
__device__ __forceinline__ void cp_async16(uint32_t s, const void* g) {
    asm volatile("cp.async.cg.shared.global [%0], [%1], 16;" :: "r"(s), "l"(g));
}
#define CP_COMMIT() asm volatile("cp.async.commit_group;")
#define CP_WAIT(n)  asm volatile("cp.async.wait_group %0;" :: "n"(n))

__device__ __forceinline__ void ldm4(uint32_t* r, uint32_t addr) {
    asm volatile("ldmatrix.sync.aligned.m8n8.x4.shared.b16 {%0,%1,%2,%3}, [%4];"
                 : "=r"(r[0]), "=r"(r[1]), "=r"(r[2]), "=r"(r[3]) : "r"(addr));
}
__device__ __forceinline__ void mma_bf16(float* d, const uint32_t* a,
                                         uint32_t b0, uint32_t b1) {
    asm volatile(
        "mma.sync.aligned.m16n8k16.row.col.f32.bf16.bf16.f32 "
        "{%0,%1,%2,%3}, {%4,%5,%6,%7}, {%8,%9}, {%0,%1,%2,%3};"
        : "+f"(d[0]), "+f"(d[1]), "+f"(d[2]), "+f"(d[3])
        : "r"(a[0]), "r"(a[1]), "r"(a[2]), "r"(a[3]), "r"(b0), "r"(b1));
}

// -------------------- weight scale: deterministic 2-pass mean|w| ----------
__global__ void wabs_partial(const float* __restrict__ w0,
                             const float* __restrict__ w1,
                             float* __restrict__ part) {
    const float* w = blockIdx.y ? w1 : w0;
    float s = 0.f;
    for (unsigned i = blockIdx.x * 256u + threadIdx.x; i < (unsigned)WN; i += 256u * 256u)
        s += fabsf(w[i]);
    __shared__ float red[256];
    red[threadIdx.x] = s;
    __syncthreads();
    for (int o = 128; o > 0; o >>= 1) {
        if ((int)threadIdx.x < o) red[threadIdx.x] += red[threadIdx.x + o];
        __syncthreads();
    }
    if (threadIdx.x == 0) part[blockIdx.y * 256 + blockIdx.x] = red[0];
}

__global__ void wscale_final(const float* __restrict__ part, float* __restrict__ ws) {
    __shared__ float red[256];
    int t = threadIdx.x;
    red[t] = part[blockIdx.x * 256 + t];
    __syncthreads();
    for (int o = 128; o > 0; o >>= 1) {
        if (t < o) red[t] += red[t + o];
        __syncthreads();
    }
    if (t == 0) ws[blockIdx.x] = fmaxf(red[0] / (float)WN, 1e-5f);
}

// -------------------- ternary weight quantization (float4 vectorized) -----
__global__ void wquant_kernel(const float* __restrict__ w0,
                              const float* __restrict__ w1,
                              __nv_bfloat16* __restrict__ q0,
                              __nv_bfloat16* __restrict__ q1,
                              const float* __restrict__ wsp) {
    const float* w = blockIdx.y ? w1 : w0;
    __nv_bfloat16* q = blockIdx.y ? q1 : q0;
    float s = wsp[blockIdx.y];
    unsigned i = blockIdx.x * 256u + threadIdx.x;
    float4 p = ((const float4*)w)[i];
    float t0 = fminf(fmaxf(rintf(p.x / s), -1.f), 1.f);
    float t1 = fminf(fmaxf(rintf(p.y / s), -1.f), 1.f);
    float t2 = fminf(fmaxf(rintf(p.z / s), -1.f), 1.f);
    float t3 = fminf(fmaxf(rintf(p.w / s), -1.f), 1.f);
    uint32_t a = (uint32_t)__bfloat16_as_ushort(__float2bfloat16(t0)) |
                 ((uint32_t)__bfloat16_as_ushort(__float2bfloat16(t1)) << 16);
    uint32_t b = (uint32_t)__bfloat16_as_ushort(__float2bfloat16(t2)) |
                 ((uint32_t)__bfloat16_as_ushort(__float2bfloat16(t3)) << 16);
    ((uint2*)q)[i] = make_uint2(a, b);
}

// -------------------- FWHT + act_quant: register radix-8 + shuffles -------
template <int NROW, int T>
__global__ void __launch_bounds__(T) fwht_q(const float* __restrict__ X,
                                            __nv_bfloat16* __restrict__ Q,
                                            float* __restrict__ Mv) {
    __shared__ float sx[T * 9 + 8];
    __shared__ float wmax[T / 32];
    __shared__ float scs;
    const int row = blockIdx.x;
    const int t = threadIdx.x;
    const int lane = t & 31;
    const int wid = t >> 5;

    float v[8];
    {
        const float4* xin = (const float4*)(X + (size_t)row * NROW) + t * 2;
        float4 p0 = xin[0], p1 = xin[1];
        v[0] = p0.x; v[1] = p0.y; v[2] = p0.z; v[3] = p0.w;
        v[4] = p1.x; v[5] = p1.y; v[6] = p1.z; v[7] = p1.w;
    }

#pragma unroll
    for (int h = 1; h <= 4; h <<= 1) {
#pragma unroll
        for (int r = 0; r < 8; r++) {
            if (!(r & h)) {
                float a = v[r], b = v[r + h];
                v[r] = a + b;
                v[r + h] = a - b;
            }
        }
    }

#pragma unroll
    for (int d = 1; d <= 16; d <<= 1) {
        bool up = (lane & d) != 0;
#pragma unroll
        for (int r = 0; r < 8; r++) {
            float o = __shfl_xor_sync(0xFFFFFFFFu, v[r], d);
            v[r] = up ? (o - v[r]) : (v[r] + o);
        }
    }

    const int base = t * 8 + (t >> 2) * 4;
#pragma unroll
    for (int d = 32; d <= T / 2; d <<= 1) {
        *(float4*)(sx + base)     = make_float4(v[0], v[1], v[2], v[3]);
        *(float4*)(sx + base + 4) = make_float4(v[4], v[5], v[6], v[7]);
        __syncthreads();
        int pt = t ^ d;
        int pb = pt * 8 + (pt >> 2) * 4;
        float4 u0 = *(float4*)(sx + pb);
        float4 u1 = *(float4*)(sx + pb + 4);
        bool up = (t & d) != 0;
        v[0] = up ? (u0.x - v[0]) : (v[0] + u0.x);
        v[1] = up ? (u0.y - v[1]) : (v[1] + u0.y);
        v[2] = up ? (u0.z - v[2]) : (v[2] + u0.z);
        v[3] = up ? (u0.w - v[3]) : (v[3] + u0.w);
        v[4] = up ? (u1.x - v[4]) : (v[4] + u1.x);
        v[5] = up ? (u1.y - v[5]) : (v[5] + u1.y);
        v[6] = up ? (u1.z - v[6]) : (v[6] + u1.z);
        v[7] = up ? (u1.w - v[7]) : (v[7] + u1.w);
        __syncthreads();
    }

    const float rn = 1.0f / sqrtf((float)NROW);
    float mx = 0.f;
#pragma unroll
    for (int r = 0; r < 8; r++) {
        v[r] *= rn;
        mx = fmaxf(mx, fabsf(v[r]));
    }
#pragma unroll
    for (int o = 16; o > 0; o >>= 1)
        mx = fmaxf(mx, __shfl_xor_sync(0xFFFFFFFFu, mx, o));
    if (lane == 0) wmax[wid] = mx;
    __syncthreads();
    if (t == 0) {
        float m = wmax[0];
#pragma unroll
        for (int i = 1; i < T / 32; i++) m = fmaxf(m, wmax[i]);
        m = fmaxf(m, 1e-5f);
        scs = 127.0f / m;
        Mv[row] = m / 127.0f;
    }
    __syncthreads();
    const float sc = scs;

    uint32_t w[4];
#pragma unroll
    for (int r = 0; r < 4; r++) {
        float q0 = rintf(v[2 * r] * sc);
        float q1 = rintf(v[2 * r + 1] * sc);
        q0 = fminf(fmaxf(q0, -127.f), 127.f);
        q1 = fminf(fmaxf(q1, -127.f), 127.f);
        uint32_t lo = (uint32_t)__bfloat16_as_ushort(__float2bfloat16(q0));
        uint32_t hi = (uint32_t)__bfloat16_as_ushort(__float2bfloat16(q1));
        w[r] = lo | (hi << 16);
    }
    uint4 st; st.x = w[0]; st.y = w[1]; st.z = w[2]; st.w = w[3];
    ((uint4*)(Q + (size_t)row * NROW))[t] = st;
}

// ------------- bf16 HMMA GEMM: D[M,N] = A[M,K] @ B[N,K]^T -----------------
// Tile: BM=128, BN=128, K-chunk=64 bf16 (128B rows), 3-stage cp.async,
// SW128 swizzle, 8 warps (2x4), warp tile 64x32, m16n8k16 bf16 f32-acc.
// 96KB smem -> 2 CTAs/SM. B fragments software-pipelined across k16 steps.
// Epilogue: y = acc * (s_w*m_row) [+ relu^2].
#define BM 128
#define BN 128
#define BKB 128   /* bytes per row per chunk = 64 bf16 */
static constexpr int GEMM_STAGE_BYTES = BM * BKB + BN * BKB;      // 32768
static constexpr int GEMM_SMEM = 3 * GEMM_STAGE_BYTES;            // 98304

template <bool RELUSQ>
__global__ void __launch_bounds__(256, 2) gemm_bf16(
    const __nv_bfloat16* __restrict__ A,
    const __nv_bfloat16* __restrict__ B,
    const float* __restrict__ rowm,
    const float* __restrict__ wscale,
    float* __restrict__ Cout,
    int KDIM, int NOUT) {
    extern __shared__ __align__(1024) char smem[];
    const int tid = threadIdx.x;
    const int wid = tid >> 5;
    const int lane = tid & 31;
    const uint32_t sb = smem_u32(smem);
    const int m0 = blockIdx.y * BM;
    const int n0 = blockIdx.x * BN;

    const char* Ab = (const char*)(A + (size_t)m0 * KDIM);
    const char* Bb = (const char*)(B + (size_t)n0 * KDIM);
    const size_t rowbytes = (size_t)KDIM * 2;
    const int C = KDIM >> 6;                    // chunks of 64 bf16 (128B)

    const int ldr = tid >> 3;                   // 0..31 (base row)
    const int ldc = (tid & 7) * 16;             // 16B chunk within 128B row

    auto load_stage = [&](int c, int st) {
        uint32_t sA = sb + (uint32_t)st * GEMM_STAGE_BYTES;
        uint32_t sB = sA + BM * BKB;
        const char* Ag = Ab + (size_t)c * BKB;
        const char* Bg = Bb + (size_t)c * BKB;
#pragma unroll
        for (int i = 0; i < 4; i++) {
            int r = ldr + i * 32;
            uint32_t so = (uint32_t)(r * BKB + ldc);
            cp_async16(sA + SWZ(so), Ag + (size_t)r * rowbytes + ldc);
        }
#pragma unroll
        for (int i = 0; i < 4; i++) {
            int r = ldr + i * 32;
            uint32_t so = (uint32_t)(r * BKB + ldc);
            cp_async16(sB + SWZ(so), Bg + (size_t)r * rowbytes + ldc);
        }
    };

    // prologue: 2 stages in flight
    load_stage(0, 0); CP_COMMIT();
    load_stage(1, 1); CP_COMMIT();

    // warp tiling: 2 (M) x 4 (N) warps, warp tile 64x32
    const int wm = (wid & 1) * 64;
    const int wn = (wid >> 1) * 32;
    // ldmatrix per-lane quadrant addressing (16 rows x 32 bytes per ldm4)
    const int q = lane >> 3;
    const int row_off = (q & 1) * 8 + (lane & 7);   // 0..15
    const int kb_off = (q >> 1) * 16;               // 0 or 16 bytes

    float acc[4][4][4];
#pragma unroll
    for (int mt = 0; mt < 4; mt++)
#pragma unroll
        for (int nt = 0; nt < 4; nt++)
#pragma unroll
            for (int r = 0; r < 4; r++) acc[mt][nt][r] = 0.f;

    int stc = 0;                                   // stage of chunk c
    for (int c = 0; c < C; c++) {
        CP_WAIT(1);
        __syncthreads();
        int st2 = stc + 2; if (st2 >= 3) st2 -= 3;
        if (c + 2 < C) load_stage(c + 2, st2);
        CP_COMMIT();                               // uniform group accounting

        uint32_t sA = sb + (uint32_t)stc * GEMM_STAGE_BYTES;
        uint32_t sB = sA + BM * BKB;

        // B-fragment software pipeline across the 4 k16 steps
        uint32_t bcur[2][4];
#pragma unroll
        for (int nh = 0; nh < 2; nh++) {
            uint32_t off = (uint32_t)((wn + nh * 16 + row_off) * BKB + kb_off);
            ldm4(bcur[nh], sB + SWZ(off));
        }
#pragma unroll
        for (int ks = 0; ks < 4; ks++) {           // 4 x k16 per 128B chunk
            uint32_t bnext[2][4];
            if (ks < 3) {
#pragma unroll
                for (int nh = 0; nh < 2; nh++) {
                    uint32_t off = (uint32_t)((wn + nh * 16 + row_off) * BKB +
                                              (ks + 1) * 32 + kb_off);
                    ldm4(bnext[nh], sB + SWZ(off));
                }
            }
#pragma unroll
            for (int mt = 0; mt < 4; mt++) {
                uint32_t afr[4];
                uint32_t off = (uint32_t)((wm + mt * 16 + row_off) * BKB +
                                          ks * 32 + kb_off);
                ldm4(afr, sA + SWZ(off));
#pragma unroll
                for (int nt = 0; nt < 4; nt++) {
                    int nh = nt >> 1, sel = nt & 1;
                    mma_bf16(acc[mt][nt], afr, bcur[nh][sel], bcur[nh][sel + 2]);
                }
            }
            if (ks < 3) {
#pragma unroll
                for (int nh = 0; nh < 2; nh++)
#pragma unroll
                    for (int r = 0; r < 4; r++) bcur[nh][r] = bnext[nh][r];
            }
        }
        __syncthreads();                 // compute done before stage reuse
        if (++stc == 3) stc = 0;
    }

    // ---- epilogue ----
    const float wsv = *wscale;
    const int lr = lane >> 2;            // 0..7
    const int lc = (lane & 3) * 2;
#pragma unroll
    for (int mt = 0; mt < 4; mt++) {
        int r0 = m0 + wm + mt * 16 + lr;
        int r1 = r0 + 8;
        float al0 = wsv * rowm[r0];
        float al1 = wsv * rowm[r1];
        float* o0 = Cout + (size_t)r0 * NOUT + n0 + wn;
        float* o1 = Cout + (size_t)r1 * NOUT + n0 + wn;
#pragma unroll
        for (int nt = 0; nt < 4; nt++) {
            int colb = nt * 8 + lc;
            float y0 = acc[mt][nt][0] * al0;
            float y1 = acc[mt][nt][1] * al0;
            float y2 = acc[mt][nt][2] * al1;
            float y3 = acc[mt][nt][3] * al1;
            if (RELUSQ) {
                y0 = y0 > 0.f ? y0 * y0 : 0.f;
                y1 = y1 > 0.f ? y1 * y1 : 0.f;
                y2 = y2 > 0.f ? y2 * y2 : 0.f;
                y3 = y3 > 0.f ? y3 * y3 : 0.f;
            }
            *(float2*)(o0 + colb) = make_float2(y0, y1);
            *(float2*)(o1 + colb) = make_float2(y2, y3);
        }
    }
}

// -------------------- host entry ------------------------------------------
extern "C" void kernel_launch(void* const* d_in, const int* in_sizes, int n_in,
                              void* d_out, int out_size) {
    const float* x  = (const float*)d_in[0];   // [4,2048,2048]
    const float* wu = (const float*)d_in[1];   // [4096,2048]
    const float* wd = (const float*)d_in[2];   // [2048,4096]
    float* out = (float*)d_out;                // [4,2048,2048]

    void *p_wqu, *p_wqd, *p_xq, *p_h, *p_hq, *p_m1, *p_m2, *p_ws, *p_part;
    cudaGetSymbolAddress(&p_wqu, g_wq_up);
    cudaGetSymbolAddress(&p_wqd, g_wq_dn);
    cudaGetSymbolAddress(&p_xq,  g_xq);
    cudaGetSymbolAddress(&p_h,   g_h);
    cudaGetSymbolAddress(&p_hq,  g_hq);
    cudaGetSymbolAddress(&p_m1,  g_m1);
    cudaGetSymbolAddress(&p_m2,  g_m2);
    cudaGetSymbolAddress(&p_ws,  g_ws);
    cudaGetSymbolAddress(&p_part, g_part);

    cudaFuncSetAttribute(gemm_bf16<true>,
                         cudaFuncAttributeMaxDynamicSharedMemorySize, GEMM_SMEM);
    cudaFuncSetAttribute(gemm_bf16<false>,
                         cudaFuncAttributeMaxDynamicSharedMemorySize, GEMM_SMEM);

    // 1) weight scales (mean|w|, deterministic two-pass)
    wabs_partial<<<dim3(256, 2), 256>>>(wu, wd, (float*)p_part);
    wscale_final<<<2, 256>>>((const float*)p_part, (float*)p_ws);

    // 2) ternary-quantize both weights into bf16 (float4 vectorized)
    wquant_kernel<<<dim3(WN / 1024, 2), 256>>>(wu, wd,
        (__nv_bfloat16*)p_wqu, (__nv_bfloat16*)p_wqd, (const float*)p_ws);

    // 3) FWHT(2048) + act quant -> bf16
    fwht_q<HK1, 256><<<MDIM, 256>>>(x, (__nv_bfloat16*)p_xq, (float*)p_m1);

    // 4) GEMM1 (8192x4096x2048) + relu^2 epilogue -> g_h (f32)
    gemm_bf16<true><<<dim3(HK2 / BN, MDIM / BM), 256, GEMM_SMEM>>>(
        (const __nv_bfloat16*)p_xq, (const __nv_bfloat16*)p_wqu,
        (const float*)p_m1, (const float*)p_ws,
        (float*)p_h, HK1, HK2);

    // 5) FWHT(4096) + act quant -> bf16
    fwht_q<HK2, 512><<<MDIM, 512>>>((const float*)p_h, (__nv_bfloat16*)p_hq, (float*)p_m2);

    // 6) GEMM2 (8192x2048x4096) -> out
    gemm_bf16<false><<<dim3(HK1 / BN, MDIM / BM), 256, GEMM_SMEM>>>(
        (const __nv_bfloat16*)p_hq, (const __nv_bfloat16*)p_wqd,
        (const float*)p_m2, (const float*)p_ws + 1,
        out, HK2, HK1);
}

// round 14
// speedup vs baseline: 1.5261x; 1.5261x over previous
#include <cuda_runtime.h>
#include <cuda_bf16.h>
#include <cstdint>

// ============================================================
// BitFeedForward (Hadamard BitLinear x2) for sm_103
// R14: exact revert to R8's proven GEMM (BM=BN=128, 64x32 warp tile,
//      3 stages, 2 CTAs/SM, straight inner loop ~120 regs).
//      R9 (64x64 tile) and R13 (fragment pipelining) both regressed:
//      occupancy + ptxas scheduling slack beat manual pipelining here.
//      Keeps R12's vectorized wquant only.
// ============================================================

#define MDIM 8192          // B*S tokens
#define HK1  2048          // hidden (layer1 K)
#define HK2  4096          // intermediate (layer2 K)
#define WN   8388608       // elements per weight (4096*2048)

// -------------------- scratch (device globals; no allocs allowed) ---------
__device__ __align__(256) __nv_bfloat16 g_wq_up[WN];
__device__ __align__(256) __nv_bfloat16 g_wq_dn[WN];
__device__ __align__(256) __nv_bfloat16 g_xq[(size_t)MDIM * HK1];
__device__ __align__(256) float         g_h [(size_t)MDIM * HK2];
__device__ __align__(256) __nv_bfloat16 g_hq[(size_t)MDIM * HK2];
__device__ float g_m1[MDIM];
__device__ float g_m2[MDIM];
__device__ float g_ws[2];
__device__ float g_part[512];

// -------------------- PTX helpers ----------------------------------------
#define SWZ(o) ((o) ^ (((o) >> 3) & 0x70))

__device__ __forceinline__ uint32_t smem_u32(const void* p) {
    uint32_t a;
    asm("{ .reg .u64 t; cvta.to.shared.u64 t, %1; cvt.u32.u64 %0, t; }"
        : "=r"(a) : "l"(p));
    return a;
}
__device__ __forceinline__ void cp_async16(uint32_t s, const void* g) {
    asm volatile("cp.async.cg.shared.global [%0], [%1], 16;" :: "r"(s), "l"(g));
}
#define CP_COMMIT() asm volatile("cp.async.commit_group;")
#define CP_WAIT(n)  asm volatile("cp.async.wait_group %0;" :: "n"(n))

__device__ __forceinline__ void ldm4(uint32_t* r, uint32_t addr) {
    asm volatile("ldmatrix.sync.aligned.m8n8.x4.shared.b16 {%0,%1,%2,%3}, [%4];"
                 : "=r"(r[0]), "=r"(r[1]), "=r"(r[2]), "=r"(r[3]) : "r"(addr));
}
__device__ __forceinline__ void mma_bf16(float* d, const uint32_t* a,
                                         uint32_t b0, uint32_t b1) {
    asm volatile(
        "mma.sync.aligned.m16n8k16.row.col.f32.bf16.bf16.f32 "
        "{%0,%1,%2,%3}, {%4,%5,%6,%7}, {%8,%9}, {%0,%1,%2,%3};"
        : "+f"(d[0]), "+f"(d[1]), "+f"(d[2]), "+f"(d[3])
        : "r"(a[0]), "r"(a[1]), "r"(a[2]), "r"(a[3]), "r"(b0), "r"(b1));
}

// -------------------- weight scale: deterministic 2-pass mean|w| ----------
__global__ void wabs_partial(const float* __restrict__ w0,
                             const float* __restrict__ w1,
                             float* __restrict__ part) {
    const float* w = blockIdx.y ? w1 : w0;
    float s = 0.f;
    for (unsigned i = blockIdx.x * 256u + threadIdx.x; i < (unsigned)WN; i += 256u * 256u)
        s += fabsf(w[i]);
    __shared__ float red[256];
    red[threadIdx.x] = s;
    __syncthreads();
    for (int o = 128; o > 0; o >>= 1) {
        if ((int)threadIdx.x < o) red[threadIdx.x] += red[threadIdx.x + o];
        __syncthreads();
    }
    if (threadIdx.x == 0) part[blockIdx.y * 256 + blockIdx.x] = red[0];
}

__global__ void wscale_final(const float* __restrict__ part, float* __restrict__ ws) {
    __shared__ float red[256];
    int t = threadIdx.x;
    red[t] = part[blockIdx.x * 256 + t];
    __syncthreads();
    for (int o = 128; o > 0; o >>= 1) {
        if (t < o) red[t] += red[t + o];
        __syncthreads();
    }
    if (t == 0) ws[blockIdx.x] = fmaxf(red[0] / (float)WN, 1e-5f);
}

// -------------------- ternary weight quantization (float4 vectorized) -----
__global__ void wquant_kernel(const float* __restrict__ w0,
                              const float* __restrict__ w1,
                              __nv_bfloat16* __restrict__ q0,
                              __nv_bfloat16* __restrict__ q1,
                              const float* __restrict__ wsp) {
    const float* w = blockIdx.y ? w1 : w0;
    __nv_bfloat16* q = blockIdx.y ? q1 : q0;
    float s = wsp[blockIdx.y];
    unsigned i = blockIdx.x * 256u + threadIdx.x;
    float4 p = ((const float4*)w)[i];
    float t0 = fminf(fmaxf(rintf(p.x / s), -1.f), 1.f);
    float t1 = fminf(fmaxf(rintf(p.y / s), -1.f), 1.f);
    float t2 = fminf(fmaxf(rintf(p.z / s), -1.f), 1.f);
    float t3 = fminf(fmaxf(rintf(p.w / s), -1.f), 1.f);
    uint32_t a = (uint32_t)__bfloat16_as_ushort(__float2bfloat16(t0)) |
                 ((uint32_t)__bfloat16_as_ushort(__float2bfloat16(t1)) << 16);
    uint32_t b = (uint32_t)__bfloat16_as_ushort(__float2bfloat16(t2)) |
                 ((uint32_t)__bfloat16_as_ushort(__float2bfloat16(t3)) << 16);
    ((uint2*)q)[i] = make_uint2(a, b);
}

// -------------------- FWHT + act_quant: register radix-8 + shuffles -------
template <int NROW, int T>
__global__ void __launch_bounds__(T) fwht_q(const float* __restrict__ X,
                                            __nv_bfloat16* __restrict__ Q,
                                            float* __restrict__ Mv) {
    __shared__ float sx[T * 9 + 8];
    __shared__ float wmax[T / 32];
    __shared__ float scs;
    const int row = blockIdx.x;
    const int t = threadIdx.x;
    const int lane = t & 31;
    const int wid = t >> 5;

    float v[8];
    {
        const float4* xin = (const float4*)(X + (size_t)row * NROW) + t * 2;
        float4 p0 = xin[0], p1 = xin[1];
        v[0] = p0.x; v[1] = p0.y; v[2] = p0.z; v[3] = p0.w;
        v[4] = p1.x; v[5] = p1.y; v[6] = p1.z; v[7] = p1.w;
    }

#pragma unroll
    for (int h = 1; h <= 4; h <<= 1) {
#pragma unroll
        for (int r = 0; r < 8; r++) {
            if (!(r & h)) {
                float a = v[r], b = v[r + h];
                v[r] = a + b;
                v[r + h] = a - b;
            }
        }
    }

#pragma unroll
    for (int d = 1; d <= 16; d <<= 1) {
        bool up = (lane & d) != 0;
#pragma unroll
        for (int r = 0; r < 8; r++) {
            float o = __shfl_xor_sync(0xFFFFFFFFu, v[r], d);
            v[r] = up ? (o - v[r]) : (v[r] + o);
        }
    }

    const int base = t * 8 + (t >> 2) * 4;
#pragma unroll
    for (int d = 32; d <= T / 2; d <<= 1) {
        *(float4*)(sx + base)     = make_float4(v[0], v[1], v[2], v[3]);
        *(float4*)(sx + base + 4) = make_float4(v[4], v[5], v[6], v[7]);
        __syncthreads();
        int pt = t ^ d;
        int pb = pt * 8 + (pt >> 2) * 4;
        float4 u0 = *(float4*)(sx + pb);
        float4 u1 = *(float4*)(sx + pb + 4);
        bool up = (t & d) != 0;
        v[0] = up ? (u0.x - v[0]) : (v[0] + u0.x);
        v[1] = up ? (u0.y - v[1]) : (v[1] + u0.y);
        v[2] = up ? (u0.z - v[2]) : (v[2] + u0.z);
        v[3] = up ? (u0.w - v[3]) : (v[3] + u0.w);
        v[4] = up ? (u1.x - v[4]) : (v[4] + u1.x);
        v[5] = up ? (u1.y - v[5]) : (v[5] + u1.y);
        v[6] = up ? (u1.z - v[6]) : (v[6] + u1.z);
        v[7] = up ? (u1.w - v[7]) : (v[7] + u1.w);
        __syncthreads();
    }

    const float rn = 1.0f / sqrtf((float)NROW);
    float mx = 0.f;
#pragma unroll
    for (int r = 0; r < 8; r++) {
        v[r] *= rn;
        mx = fmaxf(mx, fabsf(v[r]));
    }
#pragma unroll
    for (int o = 16; o > 0; o >>= 1)
        mx = fmaxf(mx, __shfl_xor_sync(0xFFFFFFFFu, mx, o));
    if (lane == 0) wmax[wid] = mx;
    __syncthreads();
    if (t == 0) {
        float m = wmax[0];
#pragma unroll
        for (int i = 1; i < T / 32; i++) m = fmaxf(m, wmax[i]);
        m = fmaxf(m, 1e-5f);
        scs = 127.0f / m;
        Mv[row] = m / 127.0f;
    }
    __syncthreads();
    const float sc = scs;

    uint32_t w[4];
#pragma unroll
    for (int r = 0; r < 4; r++) {
        float q0 = rintf(v[2 * r] * sc);
        float q1 = rintf(v[2 * r + 1] * sc);
        q0 = fminf(fmaxf(q0, -127.f), 127.f);
        q1 = fminf(fmaxf(q1, -127.f), 127.f);
        uint32_t lo = (uint32_t)__bfloat16_as_ushort(__float2bfloat16(q0));
        uint32_t hi = (uint32_t)__bfloat16_as_ushort(__float2bfloat16(q1));
        w[r] = lo | (hi << 16);
    }
    uint4 st; st.x = w[0]; st.y = w[1]; st.z = w[2]; st.w = w[3];
    ((uint4*)(Q + (size_t)row * NROW))[t] = st;
}

// ------------- bf16 HMMA GEMM: D[M,N] = A[M,K] @ B[N,K]^T -----------------
// R8-proven config: BM=128, BN=128, K-chunk=64 bf16 (128B rows), 3-stage
// cp.async, SW128 swizzle, 8 warps (2x4), warp tile 64x32, m16n8k16 bf16.
// 96KB smem -> 2 CTAs/SM. Straight load-then-MMA inner loop (~120 regs).
// Epilogue: y = acc * (s_w*m_row) [+ relu^2].
#define BM 128
#define BN 128
#define BKB 128   /* bytes per row per chunk = 64 bf16 */
static constexpr int GEMM_STAGE_BYTES = BM * BKB + BN * BKB;      // 32768
static constexpr int GEMM_SMEM = 3 * GEMM_STAGE_BYTES;            // 98304

template <bool RELUSQ>
__global__ void __launch_bounds__(256, 2) gemm_bf16(
    const __nv_bfloat16* __restrict__ A,
    const __nv_bfloat16* __restrict__ B,
    const float* __restrict__ rowm,
    const float* __restrict__ wscale,
    float* __restrict__ Cout,
    int KDIM, int NOUT) {
    extern __shared__ __align__(1024) char smem[];
    const int tid = threadIdx.x;
    const int wid = tid >> 5;
    const int lane = tid & 31;
    const uint32_t sb = smem_u32(smem);
    const int m0 = blockIdx.y * BM;
    const int n0 = blockIdx.x * BN;

    const char* Ab = (const char*)(A + (size_t)m0 * KDIM);
    const char* Bb = (const char*)(B + (size_t)n0 * KDIM);
    const size_t rowbytes = (size_t)KDIM * 2;
    const int C = KDIM >> 6;                    // chunks of 64 bf16 (128B)

    const int ldr = tid >> 3;                   // 0..31 (base row)
    const int ldc = (tid & 7) * 16;             // 16B chunk within 128B row

    auto load_stage = [&](int c, int st) {
        uint32_t sA = sb + (uint32_t)st * GEMM_STAGE_BYTES;
        uint32_t sB = sA + BM * BKB;
        const char* Ag = Ab + (size_t)c * BKB;
        const char* Bg = Bb + (size_t)c * BKB;
#pragma unroll
        for (int i = 0; i < 4; i++) {
            int r = ldr + i * 32;
            uint32_t so = (uint32_t)(r * BKB + ldc);
            cp_async16(sA + SWZ(so), Ag + (size_t)r * rowbytes + ldc);
        }
#pragma unroll
        for (int i = 0; i < 4; i++) {
            int r = ldr + i * 32;
            uint32_t so = (uint32_t)(r * BKB + ldc);
            cp_async16(sB + SWZ(so), Bg + (size_t)r * rowbytes + ldc);
        }
    };

    // prologue: 2 stages in flight
    load_stage(0, 0); CP_COMMIT();
    load_stage(1, 1); CP_COMMIT();

    // warp tiling: 2 (M) x 4 (N) warps, warp tile 64x32
    const int wm = (wid & 1) * 64;
    const int wn = (wid >> 1) * 32;
    // ldmatrix per-lane quadrant addressing (16 rows x 32 bytes per ldm4)
    const int q = lane >> 3;
    const int row_off = (q & 1) * 8 + (lane & 7);   // 0..15
    const int kb_off = (q >> 1) * 16;               // 0 or 16 bytes

    float acc[4][4][4];
#pragma unroll
    for (int mt = 0; mt < 4; mt++)
#pragma unroll
        for (int nt = 0; nt < 4; nt++)
#pragma unroll
            for (int r = 0; r < 4; r++) acc[mt][nt][r] = 0.f;

    int stc = 0;                                   // stage of chunk c
    for (int c = 0; c < C; c++) {
        CP_WAIT(1);
        __syncthreads();
        int st2 = stc + 2; if (st2 >= 3) st2 -= 3;
        if (c + 2 < C) load_stage(c + 2, st2);
        CP_COMMIT();                               // uniform group accounting

        uint32_t sA = sb + (uint32_t)stc * GEMM_STAGE_BYTES;
        uint32_t sB = sA + BM * BKB;
#pragma unroll
        for (int ks = 0; ks < 4; ks++) {           // 4 x k16 per 128B chunk
            uint32_t afr[4][4];
#pragma unroll
            for (int mt = 0; mt < 4; mt++) {
                uint32_t off = (uint32_t)((wm + mt * 16 + row_off) * BKB +
                                          ks * 32 + kb_off);
                ldm4(afr[mt], sA + SWZ(off));
            }
            uint32_t bfr[2][4];
#pragma unroll
            for (int nh = 0; nh < 2; nh++) {
                uint32_t off = (uint32_t)((wn + nh * 16 + row_off) * BKB +
                                          ks * 32 + kb_off);
                ldm4(bfr[nh], sB + SWZ(off));
            }
#pragma unroll
            for (int mt = 0; mt < 4; mt++)
#pragma unroll
                for (int nt = 0; nt < 4; nt++) {
                    int nh = nt >> 1, sel = nt & 1;
                    mma_bf16(acc[mt][nt], afr[mt], bfr[nh][sel], bfr[nh][sel + 2]);
                }
        }
        __syncthreads();                 // compute done before stage reuse
        if (++stc == 3) stc = 0;
    }

    // ---- epilogue ----
    const float wsv = *wscale;
    const int lr = lane >> 2;            // 0..7
    const int lc = (lane & 3) * 2;
#pragma unroll
    for (int mt = 0; mt < 4; mt++) {
        int r0 = m0 + wm + mt * 16 + lr;
        int r1 = r0 + 8;
        float al0 = wsv * rowm[r0];
        float al1 = wsv * rowm[r1];
        float* o0 = Cout + (size_t)r0 * NOUT + n0 + wn;
        float* o1 = Cout + (size_t)r1 * NOUT + n0 + wn;
#pragma unroll
        for (int nt = 0; nt < 4; nt++) {
            int colb = nt * 8 + lc;
            float y0 = acc[mt][nt][0] * al0;
            float y1 = acc[mt][nt][1] * al0;
            float y2 = acc[mt][nt][2] * al1;
            float y3 = acc[mt][nt][3] * al1;
            if (RELUSQ) {
                y0 = y0 > 0.f ? y0 * y0 : 0.f;
                y1 = y1 > 0.f ? y1 * y1 : 0.f;
                y2 = y2 > 0.f ? y2 * y2 : 0.f;
                y3 = y3 > 0.f ? y3 * y3 : 0.f;
            }
            *(float2*)(o0 + colb) = make_float2(y0, y1);
            *(float2*)(o1 + colb) = make_float2(y2, y3);
        }
    }
}

// -------------------- host entry ------------------------------------------
extern "C" void kernel_launch(void* const* d_in, const int* in_sizes, int n_in,
                              void* d_out, int out_size) {
    const float* x  = (const float*)d_in[0];   // [4,2048,2048]
    const float* wu = (const float*)d_in[1];   // [4096,2048]
    const float* wd = (const float*)d_in[2];   // [2048,4096]
    float* out = (float*)d_out;                // [4,2048,2048]

    void *p_wqu, *p_wqd, *p_xq, *p_h, *p_hq, *p_m1, *p_m2, *p_ws, *p_part;
    cudaGetSymbolAddress(&p_wqu, g_wq_up);
    cudaGetSymbolAddress(&p_wqd, g_wq_dn);
    cudaGetSymbolAddress(&p_xq,  g_xq);
    cudaGetSymbolAddress(&p_h,   g_h);
    cudaGetSymbolAddress(&p_hq,  g_hq);
    cudaGetSymbolAddress(&p_m1,  g_m1);
    cudaGetSymbolAddress(&p_m2,  g_m2);
    cudaGetSymbolAddress(&p_ws,  g_ws);
    cudaGetSymbolAddress(&p_part, g_part);

    cudaFuncSetAttribute(gemm_bf16<true>,
                         cudaFuncAttributeMaxDynamicSharedMemorySize, GEMM_SMEM);
    cudaFuncSetAttribute(gemm_bf16<false>,
                         cudaFuncAttributeMaxDynamicSharedMemorySize, GEMM_SMEM);

    // 1) weight scales (mean|w|, deterministic two-pass)
    wabs_partial<<<dim3(256, 2), 256>>>(wu, wd, (float*)p_part);
    wscale_final<<<2, 256>>>((const float*)p_part, (float*)p_ws);

    // 2) ternary-quantize both weights into bf16 (float4 vectorized)
    wquant_kernel<<<dim3(WN / 1024, 2), 256>>>(wu, wd,
        (__nv_bfloat16*)p_wqu, (__nv_bfloat16*)p_wqd, (const float*)p_ws);

    // 3) FWHT(2048) + act quant -> bf16
    fwht_q<HK1, 256><<<MDIM, 256>>>(x, (__nv_bfloat16*)p_xq, (float*)p_m1);

    // 4) GEMM1 (8192x4096x2048) + relu^2 epilogue -> g_h (f32)
    gemm_bf16<true><<<dim3(HK2 / BN, MDIM / BM), 256, GEMM_SMEM>>>(
        (const __nv_bfloat16*)p_xq, (const __nv_bfloat16*)p_wqu,
        (const float*)p_m1, (const float*)p_ws,
        (float*)p_h, HK1, HK2);

    // 5) FWHT(4096) + act quant -> bf16
    fwht_q<HK2, 512><<<MDIM, 512>>>((const float*)p_h, (__nv_bfloat16*)p_hq, (float*)p_m2);

    // 6) GEMM2 (8192x2048x4096) -> out
    gemm_bf16<false><<<dim3(HK1 / BN, MDIM / BM), 256, GEMM_SMEM>>>(
        (const __nv_bfloat16*)p_hq, (const __nv_bfloat16*)p_wqd,
        (const float*)p_m2, (const float*)p_ws + 1,
        out, HK2, HK1);
}

// round 16
// speedup vs baseline: 1.5393x; 1.0087x over previous
#include <cuda_runtime.h>
#include <cuda_bf16.h>
#include <cstdint>

// ============================================================
// BitFeedForward (Hadamard BitLinear x2) for sm_103
// R15: (1) GEMM mainloop single-barrier (bottom __syncthreads removed;
//          top barrier alone orders stage reuse + cp.async visibility).
//      (2) FWHT radix-16: 16 elem/thread, 4 reg + 5 shfl stages, only
//          2 (2048) / 3 (4096) smem exchange stages, t*20 pad layout.
//      GEMM topology stays R8-proven (BM=BN=128, 64x32 warp, 2 CTAs/SM).
// ============================================================

#define MDIM 8192          // B*S tokens
#define HK1  2048          // hidden (layer1 K)
#define HK2  4096          // intermediate (layer2 K)
#define WN   8388608       // elements per weight (4096*2048)

// -------------------- scratch (device globals; no allocs allowed) ---------
__device__ __align__(256) __nv_bfloat16 g_wq_up[WN];
__device__ __align__(256) __nv_bfloat16 g_wq_dn[WN];
__device__ __align__(256) __nv_bfloat16 g_xq[(size_t)MDIM * HK1];
__device__ __align__(256) float         g_h [(size_t)MDIM * HK2];
__device__ __align__(256) __nv_bfloat16 g_hq[(size_t)MDIM * HK2];
__device__ float g_m1[MDIM];
__device__ float g_m2[MDIM];
__device__ float g_ws[2];
__device__ float g_part[512];

// -------------------- PTX helpers ----------------------------------------
#define SWZ(o) ((o) ^ (((o) >> 3) & 0x70))

__device__ __forceinline__ uint32_t smem_u32(const void* p) {
    uint32_t a;
    asm("{ .reg .u64 t; cvta.to.shared.u64 t, %1; cvt.u32.u64 %0, t; }"
        : "=r"(a) : "l"(p));
    return a;
}
__device__ __forceinline__ void cp_async16(uint32_t s, const void* g) {
    asm volatile("cp.async.cg.shared.global [%0], [%1], 16;" :: "r"(s), "l"(g));
}
#define CP_COMMIT() asm volatile("cp.async.commit_group;")
#define CP_WAIT(n)  asm volatile("cp.async.wait_group %0;" :: "n"(n))

__device__ __forceinline__ void ldm4(uint32_t* r, uint32_t addr) {
    asm volatile("ldmatrix.sync.aligned.m8n8.x4.shared.b16 {%0,%1,%2,%3}, [%4];"
                 : "=r"(r[0]), "=r"(r[1]), "=r"(r[2]), "=r"(r[3]) : "r"(addr));
}
__device__ __forceinline__ void mma_bf16(float* d, const uint32_t* a,
                                         uint32_t b0, uint32_t b1) {
    asm volatile(
        "mma.sync.aligned.m16n8k16.row.col.f32.bf16.bf16.f32 "
        "{%0,%1,%2,%3}, {%4,%5,%6,%7}, {%8,%9}, {%0,%1,%2,%3};"
        : "+f"(d[0]), "+f"(d[1]), "+f"(d[2]), "+f"(d[3])
        : "r"(a[0]), "r"(a[1]), "r"(a[2]), "r"(a[3]), "r"(b0), "r"(b1));
}

// -------------------- weight scale: deterministic 2-pass mean|w| ----------
__global__ void wabs_partial(const float* __restrict__ w0,
                             const float* __restrict__ w1,
                             float* __restrict__ part) {
    const float* w = blockIdx.y ? w1 : w0;
    float s = 0.f;
    for (unsigned i = blockIdx.x * 256u + threadIdx.x; i < (unsigned)WN; i += 256u * 256u)
        s += fabsf(w[i]);
    __shared__ float red[256];
    red[threadIdx.x] = s;
    __syncthreads();
    for (int o = 128; o > 0; o >>= 1) {
        if ((int)threadIdx.x < o) red[threadIdx.x] += red[threadIdx.x + o];
        __syncthreads();
    }
    if (threadIdx.x == 0) part[blockIdx.y * 256 + blockIdx.x] = red[0];
}

__global__ void wscale_final(const float* __restrict__ part, float* __restrict__ ws) {
    __shared__ float red[256];
    int t = threadIdx.x;
    red[t] = part[blockIdx.x * 256 + t];
    __syncthreads();
    for (int o = 128; o > 0; o >>= 1) {
        if (t < o) red[t] += red[t + o];
        __syncthreads();
    }
    if (t == 0) ws[blockIdx.x] = fmaxf(red[0] / (float)WN, 1e-5f);
}

// -------------------- ternary weight quantization (float4 vectorized) -----
__global__ void wquant_kernel(const float* __restrict__ w0,
                              const float* __restrict__ w1,
                              __nv_bfloat16* __restrict__ q0,
                              __nv_bfloat16* __restrict__ q1,
                              const float* __restrict__ wsp) {
    const float* w = blockIdx.y ? w1 : w0;
    __nv_bfloat16* q = blockIdx.y ? q1 : q0;
    float s = wsp[blockIdx.y];
    unsigned i = blockIdx.x * 256u + threadIdx.x;
    float4 p = ((const float4*)w)[i];
    float t0 = fminf(fmaxf(rintf(p.x / s), -1.f), 1.f);
    float t1 = fminf(fmaxf(rintf(p.y / s), -1.f), 1.f);
    float t2 = fminf(fmaxf(rintf(p.z / s), -1.f), 1.f);
    float t3 = fminf(fmaxf(rintf(p.w / s), -1.f), 1.f);
    uint32_t a = (uint32_t)__bfloat16_as_ushort(__float2bfloat16(t0)) |
                 ((uint32_t)__bfloat16_as_ushort(__float2bfloat16(t1)) << 16);
    uint32_t b = (uint32_t)__bfloat16_as_ushort(__float2bfloat16(t2)) |
                 ((uint32_t)__bfloat16_as_ushort(__float2bfloat16(t3)) << 16);
    ((uint2*)q)[i] = make_uint2(a, b);
}

// -------------------- FWHT + act_quant: register radix-16 + shuffles ------
// Thread owns 16 consecutive elements (T = NROW/16).
//   h=1..8      : in registers (4 stages)
//   h=16..256   : warp shuffles (d = 1..16, 5 stages)
//   h>=512      : cross-warp smem exchange (d = 32..T/2: 2 or 3 stages)
// Smem layout: thread t at float offset t*20 (stride 80B). 8 consecutive
// lanes hit all eight 16B bank slots (80*8 = 5*128) -> conflict-free for
// 16B accesses; t^d partners preserve the property.
// FP op order identical to radix-8 version -> bit-identical output.
template <int NROW, int T>
__global__ void __launch_bounds__(T) fwht_q(const float* __restrict__ X,
                                            __nv_bfloat16* __restrict__ Q,
                                            float* __restrict__ Mv) {
    __shared__ float sx[T * 20];
    __shared__ float wmax[T / 32];
    __shared__ float scs;
    const int row = blockIdx.x;
    const int t = threadIdx.x;
    const int lane = t & 31;
    const int wid = t >> 5;

    float v[16];
    {
        const float4* xin = (const float4*)(X + (size_t)row * NROW) + t * 4;
#pragma unroll
        for (int r = 0; r < 4; r++) {
            float4 p = xin[r];
            v[4 * r] = p.x; v[4 * r + 1] = p.y;
            v[4 * r + 2] = p.z; v[4 * r + 3] = p.w;
        }
    }

    // in-register stages h = 1, 2, 4, 8
#pragma unroll
    for (int h = 1; h <= 8; h <<= 1) {
#pragma unroll
        for (int r = 0; r < 16; r++) {
            if (!(r & h)) {
                float a = v[r], b = v[r + h];
                v[r] = a + b;
                v[r + h] = a - b;
            }
        }
    }

    // warp-shuffle stages h = 16..256 (d = 1..16)
#pragma unroll
    for (int d = 1; d <= 16; d <<= 1) {
        bool up = (lane & d) != 0;
#pragma unroll
        for (int r = 0; r < 16; r++) {
            float o = __shfl_xor_sync(0xFFFFFFFFu, v[r], d);
            v[r] = up ? (o - v[r]) : (v[r] + o);
        }
    }

    // cross-warp stages via smem (d = 32 .. T/2)
    const int base = t * 20;
#pragma unroll
    for (int d = 32; d <= T / 2; d <<= 1) {
#pragma unroll
        for (int r = 0; r < 4; r++)
            *(float4*)(sx + base + 4 * r) =
                make_float4(v[4 * r], v[4 * r + 1], v[4 * r + 2], v[4 * r + 3]);
        __syncthreads();
        int pb = (t ^ d) * 20;
        bool up = (t & d) != 0;
#pragma unroll
        for (int r = 0; r < 4; r++) {
            float4 u = *(float4*)(sx + pb + 4 * r);
            v[4 * r]     = up ? (u.x - v[4 * r])     : (v[4 * r] + u.x);
            v[4 * r + 1] = up ? (u.y - v[4 * r + 1]) : (v[4 * r + 1] + u.y);
            v[4 * r + 2] = up ? (u.z - v[4 * r + 2]) : (v[4 * r + 2] + u.z);
            v[4 * r + 3] = up ? (u.w - v[4 * r + 3]) : (v[4 * r + 3] + u.w);
        }
        __syncthreads();
    }

    // normalize + row absmax
    const float rn = 1.0f / sqrtf((float)NROW);
    float mx = 0.f;
#pragma unroll
    for (int r = 0; r < 16; r++) {
        v[r] *= rn;
        mx = fmaxf(mx, fabsf(v[r]));
    }
#pragma unroll
    for (int o = 16; o > 0; o >>= 1)
        mx = fmaxf(mx, __shfl_xor_sync(0xFFFFFFFFu, mx, o));
    if (lane == 0) wmax[wid] = mx;
    __syncthreads();
    if (t == 0) {
        float m = wmax[0];
#pragma unroll
        for (int i = 1; i < T / 32; i++) m = fmaxf(m, wmax[i]);
        m = fmaxf(m, 1e-5f);
        scs = 127.0f / m;
        Mv[row] = m / 127.0f;
    }
    __syncthreads();
    const float sc = scs;

    // quantize, convert to bf16 (exact for ints <=127), pack 16 -> 2x16B
    uint32_t w[8];
#pragma unroll
    for (int r = 0; r < 8; r++) {
        float q0 = rintf(v[2 * r] * sc);
        float q1 = rintf(v[2 * r + 1] * sc);
        q0 = fminf(fmaxf(q0, -127.f), 127.f);
        q1 = fminf(fmaxf(q1, -127.f), 127.f);
        uint32_t lo = (uint32_t)__bfloat16_as_ushort(__float2bfloat16(q0));
        uint32_t hi = (uint32_t)__bfloat16_as_ushort(__float2bfloat16(q1));
        w[r] = lo | (hi << 16);
    }
    uint4* qp = (uint4*)(Q + (size_t)row * NROW) + t * 2;
    qp[0] = make_uint4(w[0], w[1], w[2], w[3]);
    qp[1] = make_uint4(w[4], w[5], w[6], w[7]);
}

// ------------- bf16 HMMA GEMM: D[M,N] = A[M,K] @ B[N,K]^T -----------------
// R8-proven config: BM=128, BN=128, K-chunk=64 bf16 (128B rows), 3-stage
// cp.async, SW128 swizzle, 8 warps (2x4), warp tile 64x32, m16n8k16 bf16.
// 96KB smem -> 2 CTAs/SM. Single barrier per mainloop iteration.
// Epilogue: y = acc * (s_w*m_row) [+ relu^2].
#define BM 128
#define BN 128
#define BKB 128   /* bytes per row per chunk = 64 bf16 */
static constexpr int GEMM_STAGE_BYTES = BM * BKB + BN * BKB;      // 32768
static constexpr int GEMM_SMEM = 3 * GEMM_STAGE_BYTES;            // 98304

template <bool RELUSQ>
__global__ void __launch_bounds__(256, 2) gemm_bf16(
    const __nv_bfloat16* __restrict__ A,
    const __nv_bfloat16* __restrict__ B,
    const float* __restrict__ rowm,
    const float* __restrict__ wscale,
    float* __restrict__ Cout,
    int KDIM, int NOUT) {
    extern __shared__ __align__(1024) char smem[];
    const int tid = threadIdx.x;
    const int wid = tid >> 5;
    const int lane = tid & 31;
    const uint32_t sb = smem_u32(smem);
    const int m0 = blockIdx.y * BM;
    const int n0 = blockIdx.x * BN;

    const char* Ab = (const char*)(A + (size_t)m0 * KDIM);
    const char* Bb = (const char*)(B + (size_t)n0 * KDIM);
    const size_t rowbytes = (size_t)KDIM * 2;
    const int C = KDIM >> 6;                    // chunks of 64 bf16 (128B)

    const int ldr = tid >> 3;                   // 0..31 (base row)
    const int ldc = (tid & 7) * 16;             // 16B chunk within 128B row

    auto load_stage = [&](int c, int st) {
        uint32_t sA = sb + (uint32_t)st * GEMM_STAGE_BYTES;
        uint32_t sB = sA + BM * BKB;
        const char* Ag = Ab + (size_t)c * BKB;
        const char* Bg = Bb + (size_t)c * BKB;
#pragma unroll
        for (int i = 0; i < 4; i++) {
            int r = ldr + i * 32;
            uint32_t so = (uint32_t)(r * BKB + ldc);
            cp_async16(sA + SWZ(so), Ag + (size_t)r * rowbytes + ldc);
        }
#pragma unroll
        for (int i = 0; i < 4; i++) {
            int r = ldr + i * 32;
            uint32_t so = (uint32_t)(r * BKB + ldc);
            cp_async16(sB + SWZ(so), Bg + (size_t)r * rowbytes + ldc);
        }
    };

    // prologue: 2 stages in flight
    load_stage(0, 0); CP_COMMIT();
    load_stage(1, 1); CP_COMMIT();

    // warp tiling: 2 (M) x 4 (N) warps, warp tile 64x32
    const int wm = (wid & 1) * 64;
    const int wn = (wid >> 1) * 32;
    // ldmatrix per-lane quadrant addressing (16 rows x 32 bytes per ldm4)
    const int q = lane >> 3;
    const int row_off = (q & 1) * 8 + (lane & 7);   // 0..15
    const int kb_off = (q >> 1) * 16;               // 0 or 16 bytes

    float acc[4][4][4];
#pragma unroll
    for (int mt = 0; mt < 4; mt++)
#pragma unroll
        for (int nt = 0; nt < 4; nt++)
#pragma unroll
            for (int r = 0; r < 4; r++) acc[mt][nt][r] = 0.f;

    int stc = 0;                                   // stage of chunk c
    for (int c = 0; c < C; c++) {
        CP_WAIT(1);
        __syncthreads();
        // Single barrier: it orders (a) chunk c's cp.async data visible to
        // all warps, and (b) all warps done computing chunk c-1, whose
        // stage (stc+2 mod 3) is exactly where chunk c+2 is loaded below.
        int st2 = stc + 2; if (st2 >= 3) st2 -= 3;
        if (c + 2 < C) load_stage(c + 2, st2);
        CP_COMMIT();                               // uniform group accounting

        uint32_t sA = sb + (uint32_t)stc * GEMM_STAGE_BYTES;
        uint32_t sB = sA + BM * BKB;
#pragma unroll
        for (int ks = 0; ks < 4; ks++) {           // 4 x k16 per 128B chunk
            uint32_t afr[4][4];
#pragma unroll
            for (int mt = 0; mt < 4; mt++) {
                uint32_t off = (uint32_t)((wm + mt * 16 + row_off) * BKB +
                                          ks * 32 + kb_off);
                ldm4(afr[mt], sA + SWZ(off));
            }
            uint32_t bfr[2][4];
#pragma unroll
            for (int nh = 0; nh < 2; nh++) {
                uint32_t off = (uint32_t)((wn + nh * 16 + row_off) * BKB +
                                          ks * 32 + kb_off);
                ldm4(bfr[nh], sB + SWZ(off));
            }
#pragma unroll
            for (int mt = 0; mt < 4; mt++)
#pragma unroll
                for (int nt = 0; nt < 4; nt++) {
                    int nh = nt >> 1, sel = nt & 1;
                    mma_bf16(acc[mt][nt], afr[mt], bfr[nh][sel], bfr[nh][sel + 2]);
                }
        }
        if (++stc == 3) stc = 0;
    }

    // ---- epilogue ----
    const float wsv = *wscale;
    const int lr = lane >> 2;            // 0..7
    const int lc = (lane & 3) * 2;
#pragma unroll
    for (int mt = 0; mt < 4; mt++) {
        int r0 = m0 + wm + mt * 16 + lr;
        int r1 = r0 + 8;
        float al0 = wsv * rowm[r0];
        float al1 = wsv * rowm[r1];
        float* o0 = Cout + (size_t)r0 * NOUT + n0 + wn;
        float* o1 = Cout + (size_t)r1 * NOUT + n0 + wn;
#pragma unroll
        for (int nt = 0; nt < 4; nt++) {
            int colb = nt * 8 + lc;
            float y0 = acc[mt][nt][0] * al0;
            float y1 = acc[mt][nt][1] * al0;
            float y2 = acc[mt][nt][2] * al1;
            float y3 = acc[mt][nt][3] * al1;
            if (RELUSQ) {
                y0 = y0 > 0.f ? y0 * y0 : 0.f;
                y1 = y1 > 0.f ? y1 * y1 : 0.f;
                y2 = y2 > 0.f ? y2 * y2 : 0.f;
                y3 = y3 > 0.f ? y3 * y3 : 0.f;
            }
            *(float2*)(o0 + colb) = make_float2(y0, y1);
            *(float2*)(o1 + colb) = make_float2(y2, y3);
        }
    }
}

// -------------------- host entry ------------------------------------------
extern "C" void kernel_launch(void* const* d_in, const int* in_sizes, int n_in,
                              void* d_out, int out_size) {
    const float* x  = (const float*)d_in[0];   // [4,2048,2048]
    const float* wu = (const float*)d_in[1];   // [4096,2048]
    const float* wd = (const float*)d_in[2];   // [2048,4096]
    float* out = (float*)d_out;                // [4,2048,2048]

    void *p_wqu, *p_wqd, *p_xq, *p_h, *p_hq, *p_m1, *p_m2, *p_ws, *p_part;
    cudaGetSymbolAddress(&p_wqu, g_wq_up);
    cudaGetSymbolAddress(&p_wqd, g_wq_dn);
    cudaGetSymbolAddress(&p_xq,  g_xq);
    cudaGetSymbolAddress(&p_h,   g_h);
    cudaGetSymbolAddress(&p_hq,  g_hq);
    cudaGetSymbolAddress(&p_m1,  g_m1);
    cudaGetSymbolAddress(&p_m2,  g_m2);
    cudaGetSymbolAddress(&p_ws,  g_ws);
    cudaGetSymbolAddress(&p_part, g_part);

    cudaFuncSetAttribute(gemm_bf16<true>,
                         cudaFuncAttributeMaxDynamicSharedMemorySize, GEMM_SMEM);
    cudaFuncSetAttribute(gemm_bf16<false>,
                         cudaFuncAttributeMaxDynamicSharedMemorySize, GEMM_SMEM);

    // 1) weight scales (mean|w|, deterministic two-pass)
    wabs_partial<<<dim3(256, 2), 256>>>(wu, wd, (float*)p_part);
    wscale_final<<<2, 256>>>((const float*)p_part, (float*)p_ws);

    // 2) ternary-quantize both weights into bf16 (float4 vectorized)
    wquant_kernel<<<dim3(WN / 1024, 2), 256>>>(wu, wd,
        (__nv_bfloat16*)p_wqu, (__nv_bfloat16*)p_wqd, (const float*)p_ws);

    // 3) FWHT(2048) + act quant -> bf16  (radix-16: 128 threads)
    fwht_q<HK1, 128><<<MDIM, 128>>>(x, (__nv_bfloat16*)p_xq, (float*)p_m1);

    // 4) GEMM1 (8192x4096x2048) + relu^2 epilogue -> g_h (f32)
    gemm_bf16<true><<<dim3(HK2 / BN, MDIM / BM), 256, GEMM_SMEM>>>(
        (const __nv_bfloat16*)p_xq, (const __nv_bfloat16*)p_wqu,
        (const float*)p_m1, (const float*)p_ws,
        (float*)p_h, HK1, HK2);

    // 5) FWHT(4096) + act quant -> bf16  (radix-16: 256 threads)
    fwht_q<HK2, 256><<<MDIM, 256>>>((const float*)p_h, (__nv_bfloat16*)p_hq, (float*)p_m2);

    // 6) GEMM2 (8192x2048x4096) -> out
    gemm_bf16<false><<<dim3(HK1 / BN, MDIM / BM), 256, GEMM_SMEM>>>(
        (const __nv_bfloat16*)p_hq, (const __nv_bfloat16*)p_wqd,
        (const float*)p_m2, (const float*)p_ws + 1,
        out, HK2, HK1);
}